// round 10
// baseline (speedup 1.0000x reference)
#include <cuda_runtime.h>
#include <cuda_fp16.h>
#include <math.h>
#include <stdint.h>

// ---------------------------------------------------------------- constants
#define N_TOK 16384
#define NE    4096
#define ED    64
#define BM    128          // tokens per CTA
#define BN    128          // codes per chunk
#define NCH   (NE/BN)      // 32
#define NBLK  (N_TOK/BM)   // 128
#define NTHR  512
#define EPSW  4.0e-5f      // ref reorder slack (~1.5e-5) + 2x fp16-drop bound + margin

#define OUT_ZQ_OFF   1
#define OUT_IDX_OFF  (1 + (size_t)N_TOK*ED)
#define OUT_PERP_OFF (OUT_IDX_OFF + N_TOK)

// SMEM layout of vq_main
#define OFF_A    0                 // zh 16K + zl 16K
#define OFF_B    32768             // 2 bufs x 16K (eh only)
#define OFF_SES  65536             // 16K fp32 ||e||^2
#define SMEM_MAIN (OFF_SES + NE*4) // 81920

// ---------------------------------------------------------------- scratch
__device__ __align__(16) __half d_zh[N_TOK*ED];   // hi(-2z)
__device__ __align__(16) __half d_zl[N_TOK*ED];   // lo(-2z)
__device__ __align__(16) __half d_eh[NE*ED];      // hi(e)
__device__ __align__(16) float  d_cbT[ED*NE];     // fp32 codebook transposed [d][k]
__device__ float d_sz[N_TOK];
__device__ float d_se[NE];
__device__ int   d_counts[NE];
__device__ float d_losstok[N_TOK];
__device__ __align__(16) float d_bd[(size_t)N_TOK*16];   // 16 candidates/token
__device__ __align__(16) int   d_bi[(size_t)N_TOK*16];

// ---------------------------------------------------------------- utils
static __device__ __forceinline__ uint32_t smem_u32(const void* p) {
    uint32_t a;
    asm("{ .reg .u64 t; cvta.to.shared.u64 t, %1; cvt.u32.u64 %0, t; }"
        : "=r"(a) : "l"(p));
    return a;
}
static __device__ __forceinline__ uint32_t swz(uint32_t o) { return o ^ ((o >> 3) & 0x70); }

static __device__ __forceinline__ void ldsm4(uint32_t& r0, uint32_t& r1,
                                             uint32_t& r2, uint32_t& r3, uint32_t a) {
    asm volatile("ldmatrix.sync.aligned.m8n8.x4.shared.b16 {%0,%1,%2,%3}, [%4];"
                 : "=r"(r0), "=r"(r1), "=r"(r2), "=r"(r3) : "r"(a));
}
static __device__ __forceinline__ void mma_f16(float c[4], const uint32_t a[4],
                                               uint32_t b0, uint32_t b1) {
    asm volatile("mma.sync.aligned.m16n8k16.row.col.f32.f16.f16.f32 "
                 "{%0,%1,%2,%3}, {%4,%5,%6,%7}, {%8,%9}, {%0,%1,%2,%3};"
                 : "+f"(c[0]), "+f"(c[1]), "+f"(c[2]), "+f"(c[3])
                 : "r"(a[0]), "r"(a[1]), "r"(a[2]), "r"(a[3]), "r"(b0), "r"(b1));
}
#define CP_ASYNC16(s, g) \
    asm volatile("cp.async.cg.shared.global [%0], [%1], 16;" :: "r"(s), "l"(g))
#define CP_COMMIT() asm volatile("cp.async.commit_group;" ::: "memory")
#define CP_WAIT(n)  asm volatile("cp.async.wait_group %0;" :: "n"(n) : "memory")

#define UPD2(v0, i0, v1, i1, dv, kk) do { \
    bool _p0 = (dv) < (v0); \
    bool _p1 = (dv) < (v1); \
    (v1) = _p0 ? (v0) : (_p1 ? (dv) : (v1)); \
    (i1) = _p0 ? (i0) : (_p1 ? (kk) : (i1)); \
    (v0) = _p0 ? (dv) : (v0); \
    (i0) = _p0 ? (kk) : (i0); \
} while (0)

// exact reference-chain distance; sequential FMA d=0..63 (bit-matched in R1)
static __device__ __forceinline__ float exact_chain(const float* __restrict__ z,
                                                    const float* __restrict__ cb,
                                                    int t, int k) {
    const float4* z4 = (const float4*)(z + (size_t)t * ED);
    const float4* c4 = (const float4*)(cb + (size_t)k * ED);
    float dot = 0.f;
    #pragma unroll
    for (int q = 0; q < 16; q++) {
        float4 a = z4[q], b = c4[q];
        dot = __fmaf_rn(a.x, b.x, dot);
        dot = __fmaf_rn(a.y, b.y, dot);
        dot = __fmaf_rn(a.z, b.z, dot);
        dot = __fmaf_rn(a.w, b.w, dot);
    }
    return __fmaf_rn(-2.0f, dot, __fadd_rn(d_sz[t], d_se[k]));
}

// ---------------------------------------------------------------- L1: prep
__global__ void __launch_bounds__(256) vq_prep(const float* __restrict__ z,
                                               const float* __restrict__ cb) {
    int b = blockIdx.x, tid = threadIdx.x;
    int w = tid >> 5, lane = tid & 31;
    int row = b * 8 + w;
    bool isz = row < N_TOK;
    const float* src = isz ? z : cb;
    int r = isz ? row : row - N_TOK;

    float2 v = *(const float2*)&src[(size_t)r * ED + lane * 2];
    float sc = isz ? -2.0f : 1.0f;
    float m0 = sc * v.x, m1 = sc * v.y;
    __half h0 = __float2half_rn(m0), h1 = __float2half_rn(m1);
    __half2 hh; hh.x = h0; hh.y = h1;
    if (isz) {
        float l0 = m0 - __half2float(h0), l1 = m1 - __half2float(h1);
        __half2 ll; ll.x = __float2half_rn(l0); ll.y = __float2half_rn(l1);
        ((__half2*)d_zh)[(size_t)r * 32 + lane] = hh;
        ((__half2*)d_zl)[(size_t)r * 32 + lane] = ll;
    } else {
        ((__half2*)d_eh)[(size_t)r * 32 + lane] = hh;
        // transposed fp32 codebook for coalesced exact scans
        d_cbT[(size_t)(2 * lane)     * NE + r] = v.x;
        d_cbT[(size_t)(2 * lane + 1) * NE + r] = v.y;
    }

    float s = __fmaf_rn(v.x, v.x, v.y * v.y);
    #pragma unroll
    for (int o = 16; o; o >>= 1) s += __shfl_xor_sync(0xffffffffu, s, o);
    if (lane == 0) (isz ? d_sz : d_se)[r] = s;
}

// ---------------------------------------------------------------- L2: zero
__global__ void __launch_bounds__(256) vq_zero() {
    int i = blockIdx.x * 256 + threadIdx.x;
    if (i < NE) d_counts[i] = 0;
}

// ---------------------------------------------------------------- L3: main
static __device__ __forceinline__ void load_b(uint32_t sb, int ch, int buf) {
    int tid = threadIdx.x;
    size_t k0 = (size_t)ch * BN;
    uint32_t bh = sb + OFF_B + (uint32_t)buf * 16384u;
    #pragma unroll
    for (int p = 0; p < 2; p++) {
        int l = tid + p * NTHR;
        int row = l >> 3, seg = l & 7;
        uint32_t sw = swz((uint32_t)(row * 128 + seg * 16));
        size_t g = ((k0 + row) * ED + seg * 8) * 2;
        CP_ASYNC16(bh + sw, (const char*)d_eh + g);
    }
}

__global__ void __launch_bounds__(NTHR, 1) vq_main() {
    extern __shared__ char smem[];
    uint32_t sb = smem_u32(smem);
    const int tid = threadIdx.x;
    const int w = tid >> 5, lid = tid & 31;
    const int rowgrp = w & 7;
    const int nhalf = w >> 3;
    const int m0 = blockIdx.x * BM;

    #pragma unroll
    for (int p = 0; p < 2; p++) {
        int l = tid + p * NTHR;
        int row = l >> 3, seg = l & 7;
        uint32_t sw = swz((uint32_t)(row * 128 + seg * 16));
        size_t g = (((size_t)(m0 + row)) * ED + seg * 8) * 2;
        *(uint4*)(smem + OFF_A + sw)         = *(const uint4*)((const char*)d_zh + g);
        *(uint4*)(smem + OFF_A + 16384 + sw) = *(const uint4*)((const char*)d_zl + g);
    }
    float* ses = (float*)(smem + OFF_SES);
    for (int i = tid; i < NE; i += NTHR) ses[i] = d_se[i];
    __syncthreads();

    uint32_t ah[4][4], al[4][4];
    {
        int arow = rowgrp * 16 + (lid & 7) + ((lid >> 3) & 1) * 8;
        #pragma unroll
        for (int ks = 0; ks < 4; ks++) {
            uint32_t off = swz((uint32_t)(arow * 128 + ks * 32 + (lid >> 4) * 16));
            ldsm4(ah[ks][0], ah[ks][1], ah[ks][2], ah[ks][3], sb + OFF_A + off);
            ldsm4(al[ks][0], al[ks][1], al[ks][2], al[ks][3], sb + OFF_A + 16384u + off);
        }
    }

    float v00 = 3.4e38f, v01 = 3.4e38f, v10 = 3.4e38f, v11 = 3.4e38f;
    int   i00 = 0x7fffffff, i01 = 0x7fffffff, i10 = 0x7fffffff, i11 = 0x7fffffff;

    load_b(sb, 0, 0);
    CP_COMMIT();

    const int brow_l = (lid & 7) + ((lid >> 3) & 1) * 8;
    const int boff_l = (lid >> 4) * 16;

    for (int ch = 0; ch < NCH; ch++) {
        if (ch + 1 < NCH) { load_b(sb, ch + 1, (ch + 1) & 1); CP_COMMIT(); }
        if (ch + 1 < NCH) CP_WAIT(1); else CP_WAIT(0);
        __syncthreads();

        uint32_t bbase = sb + OFF_B + (uint32_t)((ch & 1) * 16384);

        #pragma unroll
        for (int nt2 = 0; nt2 < 4; nt2++) {
            int codebase = nhalf * 64 + nt2 * 16;
            float aE[4] = {0.f, 0.f, 0.f, 0.f};
            float aO[4] = {0.f, 0.f, 0.f, 0.f};
            #pragma unroll
            for (int ks = 0; ks < 4; ks++) {
                uint32_t sa = swz((uint32_t)((codebase + brow_l) * 128 + ks * 32 + boff_l));
                uint32_t h0, h1, h2, h3;
                ldsm4(h0, h1, h2, h3, bbase + sa);
                mma_f16(aE, ah[ks], h0, h2);
                mma_f16(aO, ah[ks], h1, h3);
                mma_f16(aE, al[ks], h0, h2);
                mma_f16(aO, al[ks], h1, h3);
            }
            int cE = codebase + 2 * (lid & 3);
            float2 sE = *(const float2*)&ses[ch * BN + cE];
            float2 sO = *(const float2*)&ses[ch * BN + cE + 8];
            int kg = ch * BN + cE;
            float dv;
            dv = __fadd_rn(aE[0], sE.x); UPD2(v00, i00, v01, i01, dv, kg);
            dv = __fadd_rn(aE[1], sE.y); UPD2(v00, i00, v01, i01, dv, kg + 1);
            dv = __fadd_rn(aO[0], sO.x); UPD2(v00, i00, v01, i01, dv, kg + 8);
            dv = __fadd_rn(aO[1], sO.y); UPD2(v00, i00, v01, i01, dv, kg + 9);
            dv = __fadd_rn(aE[2], sE.x); UPD2(v10, i10, v11, i11, dv, kg);
            dv = __fadd_rn(aE[3], sE.y); UPD2(v10, i10, v11, i11, dv, kg + 1);
            dv = __fadd_rn(aO[2], sO.x); UPD2(v10, i10, v11, i11, dv, kg + 8);
            dv = __fadd_rn(aO[3], sO.y); UPD2(v10, i10, v11, i11, dv, kg + 9);
        }
        __syncthreads();
    }

    int t0 = m0 + rowgrp * 16 + (lid >> 2);
    int slot = nhalf * 8 + (lid & 3) * 2;
    *(float2*)(d_bd + (size_t)t0 * 16 + slot)       = make_float2(v00, v01);
    *(int2*)  (d_bi + (size_t)t0 * 16 + slot)       = make_int2(i00, i01);
    *(float2*)(d_bd + (size_t)(t0 + 8) * 16 + slot) = make_float2(v10, v11);
    *(int2*)  (d_bi + (size_t)(t0 + 8) * 16 + slot) = make_int2(i10, i11);
}

// ---------------------------------------------------------------- L4: resolve
// Warp per token: certify / rescore candidates / coalesced full scan; then
// write idx, zq, loss, counts inline.
__global__ void __launch_bounds__(256) vq_resolve(const float* __restrict__ z,
                                                  const float* __restrict__ cb,
                                                  float* __restrict__ out) {
    __shared__ float s_z[8][64];
    int t = (blockIdx.x * 256 + threadIdx.x) >> 5;
    int w = (threadIdx.x >> 5), l = threadIdx.x & 31;

    float v = 3.4e38f; int ix = 0x7fffffff;
    if (l < 16) { v = d_bd[(size_t)t * 16 + l]; ix = d_bi[(size_t)t * 16 + l]; }

    // warp min with index tie-break
    float gv = v; int gi = ix;
    #pragma unroll
    for (int o = 16; o; o >>= 1) {
        float ov = __shfl_xor_sync(0xffffffffu, gv, o);
        int   oi = __shfl_xor_sync(0xffffffffu, gi, o);
        if (ov < gv || (ov == gv && oi < gi)) { gv = ov; gi = oi; }
    }
    float thr = gv + EPSW;
    bool inw = (l < 16) && (v <= thr);
    unsigned deepm = __ballot_sync(0xffffffffu, inw && (l & 1));
    unsigned candm = __ballot_sync(0xffffffffu, inw);

    int winner = gi;
    if (deepm) {
        // full exact scan, coalesced via cbT; z row staged in smem
        s_z[w][l]      = z[(size_t)t * ED + l];
        s_z[w][l + 32] = z[(size_t)t * ED + 32 + l];
        __syncwarp();
        float szt = d_sz[t];
        float bv = 3.4e38f; int bk = 0x7fffffff;
        for (int k0 = 0; k0 < NE; k0 += 32) {
            int k = k0 + l;
            float dot = 0.f;
            #pragma unroll
            for (int d = 0; d < ED; d++)
                dot = __fmaf_rn(s_z[w][d], d_cbT[(size_t)d * NE + k], dot);
            float dv = __fmaf_rn(-2.0f, dot, __fadd_rn(szt, d_se[k]));
            if (dv < bv) { bv = dv; bk = k; }        // increasing k per lane
        }
        #pragma unroll
        for (int o = 16; o; o >>= 1) {
            float ov = __shfl_xor_sync(0xffffffffu, bv, o);
            int   oi = __shfl_xor_sync(0xffffffffu, bk, o);
            if (ov < bv || (ov == bv && oi < bk)) { bv = ov; bk = oi; }
        }
        winner = bk;
    } else if (__popc(candm) > 1) {
        // exact rescore of in-window candidates (<=16 scattered rows, rare)
        float bv = 3.4e38f; int bk = 0x7fffffff;
        if (inw) { bv = exact_chain(z, cb, t, ix); bk = ix; }
        #pragma unroll
        for (int o = 16; o; o >>= 1) {
            float ov = __shfl_xor_sync(0xffffffffu, bv, o);
            int   oi = __shfl_xor_sync(0xffffffffu, bk, o);
            if (ov < bv || (ov == bv && oi < bk)) { bv = ov; bk = oi; }
        }
        winner = bk;
    }

    if (l == 0) {
        out[OUT_IDX_OFF + t] = (float)winner;
        atomicAdd(&d_counts[winner], 1);
    }
    float lacc = 0.f;
    #pragma unroll
    for (int p = 0; p < 2; p++) {
        int d = l + p * 32;
        float zq = cb[(size_t)winner * ED + d];
        float zv = z[(size_t)t * ED + d];
        float tt = __fsub_rn(zq, zv);
        out[OUT_ZQ_OFF + (size_t)t * ED + d] = __fadd_rn(zv, tt);
        lacc = __fmaf_rn(tt, tt, lacc);
    }
    #pragma unroll
    for (int o = 16; o; o >>= 1) lacc += __shfl_xor_sync(0xffffffffu, lacc, o);
    if (l == 0) d_losstok[t] = lacc;
}

// ---------------------------------------------------------------- L5: finalize
__global__ void __launch_bounds__(1024) vq_finalize(float* __restrict__ out) {
    __shared__ double sh[1024];
    int tid = threadIdx.x;
    double s = 0.0;
    for (int i = tid; i < N_TOK; i += 1024) s += (double)d_losstok[i];
    sh[tid] = s;
    __syncthreads();
    #pragma unroll
    for (int st = 512; st > 0; st >>= 1) {
        if (tid < st) sh[tid] += sh[tid + st];
        __syncthreads();
    }
    if (tid == 0)
        out[0] = (float)(1.25 * sh[0] / (double)((size_t)N_TOK * ED));
    __syncthreads();

    double h = 0.0;
    for (int i = tid; i < NE; i += 1024) {
        float em = (float)d_counts[i] / (float)N_TOK;
        h += (double)(em * logf(em + 1e-10f));
    }
    sh[tid] = h;
    __syncthreads();
    #pragma unroll
    for (int st = 512; st > 0; st >>= 1) {
        if (tid < st) sh[tid] += sh[tid + st];
        __syncthreads();
    }
    if (tid == 0)
        out[OUT_PERP_OFF] = expf(-(float)sh[0]);
}

// ---------------------------------------------------------------- launch
extern "C" void kernel_launch(void* const* d_in, const int* in_sizes, int n_in,
                              void* d_out, int out_size) {
    const float* z  = (const float*)d_in[0];
    const float* cb = (const float*)d_in[1];
    float* out = (float*)d_out;

    cudaFuncSetAttribute(vq_main, cudaFuncAttributeMaxDynamicSharedMemorySize, SMEM_MAIN);

    vq_prep<<<2560, 256>>>(z, cb);            // L1
    vq_zero<<<16, 256>>>();                   // L2
    vq_main<<<NBLK, NTHR, SMEM_MAIN>>>();     // L3
    vq_resolve<<<N_TOK / 8, 256>>>(z, cb, out); // L4  <- 6th overall: profiled
    vq_finalize<<<1, 1024>>>(out);            // L5
}

// round 11
// speedup vs baseline: 1.7027x; 1.7027x over previous
#include <cuda_runtime.h>
#include <cuda_fp16.h>
#include <math.h>
#include <stdint.h>

// ---------------------------------------------------------------- constants
#define N_TOK 16384
#define NE    4096
#define ED    64
#define BM    128          // tokens per CTA
#define BN    128          // codes per chunk
#define NCH   (NE/BN)      // 32
#define NBLK  (N_TOK/BM)   // 128
#define NTHR  512
#define EPSW  5.0e-5f      // ref 64-grid slack (1.5e-5) + dropped-term bound (1.5e-5) + margin

#define OUT_ZQ_OFF   1
#define OUT_IDX_OFF  (1 + (size_t)N_TOK*ED)
#define OUT_PERP_OFF (OUT_IDX_OFF + N_TOK)

// SMEM layout of vq_main
#define OFF_A    0                 // zh 16K + zl 16K
#define OFF_B    32768             // 2 bufs x 16K (eh only)
#define OFF_SES  65536             // 16K fp32 ||e||^2
#define SMEM_MAIN (OFF_SES + NE*4) // 81920

// ---------------------------------------------------------------- scratch
__device__ __align__(16) __half d_zh[N_TOK*ED];   // hi(-2z)
__device__ __align__(16) __half d_zl[N_TOK*ED];   // lo(-2z)
__device__ __align__(16) __half d_eh[NE*ED];      // hi(e)
__device__ __align__(16) float  d_cbT[ED*NE];     // fp32 codebook transposed [d][k]
__device__ float d_sz[N_TOK];
__device__ float d_se[NE];
__device__ int   d_counts[NE];
__device__ float d_losstok[N_TOK];
__device__ __align__(16) float d_bd[(size_t)N_TOK*16];   // best-2/thread: 16 cands/token
__device__ __align__(16) int   d_bi[(size_t)N_TOK*16];
__device__ float d_b2[(size_t)N_TOK*8];                  // 3rd-best value/thread
__device__ int   d_flag[N_TOK];
__device__ int   d_nflag;

// ---------------------------------------------------------------- utils
static __device__ __forceinline__ uint32_t smem_u32(const void* p) {
    uint32_t a;
    asm("{ .reg .u64 t; cvta.to.shared.u64 t, %1; cvt.u32.u64 %0, t; }"
        : "=r"(a) : "l"(p));
    return a;
}
static __device__ __forceinline__ uint32_t swz(uint32_t o) { return o ^ ((o >> 3) & 0x70); }

static __device__ __forceinline__ void ldsm4(uint32_t& r0, uint32_t& r1,
                                             uint32_t& r2, uint32_t& r3, uint32_t a) {
    asm volatile("ldmatrix.sync.aligned.m8n8.x4.shared.b16 {%0,%1,%2,%3}, [%4];"
                 : "=r"(r0), "=r"(r1), "=r"(r2), "=r"(r3) : "r"(a));
}
static __device__ __forceinline__ void mma_f16(float c[4], const uint32_t a[4],
                                               uint32_t b0, uint32_t b1) {
    asm volatile("mma.sync.aligned.m16n8k16.row.col.f32.f16.f16.f32 "
                 "{%0,%1,%2,%3}, {%4,%5,%6,%7}, {%8,%9}, {%0,%1,%2,%3};"
                 : "+f"(c[0]), "+f"(c[1]), "+f"(c[2]), "+f"(c[3])
                 : "r"(a[0]), "r"(a[1]), "r"(a[2]), "r"(a[3]), "r"(b0), "r"(b1));
}
#define CP_ASYNC16(s, g) \
    asm volatile("cp.async.cg.shared.global [%0], [%1], 16;" :: "r"(s), "l"(g))
#define CP_COMMIT() asm volatile("cp.async.commit_group;" ::: "memory")
#define CP_WAIT(n)  asm volatile("cp.async.wait_group %0;" :: "n"(n) : "memory")

// branchless best-3 (3rd value-only); strict < + increasing-k keeps first index
#define UPD3(v0, i0, v1, i1, v2, dv, kk) do { \
    bool _p0 = (dv) < (v0); \
    bool _p1 = (dv) < (v1); \
    bool _p2 = (dv) < (v2); \
    (v2) = _p1 ? (v1) : (_p2 ? (dv) : (v2)); \
    (v1) = _p0 ? (v0) : (_p1 ? (dv) : (v1)); \
    (i1) = _p0 ? (i0) : (_p1 ? (kk) : (i1)); \
    (v0) = _p0 ? (dv) : (v0); \
    (i0) = _p0 ? (kk) : (i0); \
} while (0)

// exact reference-chain distance; sequential FMA d=0..63 (bit-matched in R1)
static __device__ __forceinline__ float exact_chain(const float* __restrict__ z,
                                                    const float* __restrict__ cb,
                                                    int t, int k) {
    const float4* z4 = (const float4*)(z + (size_t)t * ED);
    const float4* c4 = (const float4*)(cb + (size_t)k * ED);
    float dot = 0.f;
    #pragma unroll
    for (int q = 0; q < 16; q++) {
        float4 a = z4[q], b = c4[q];
        dot = __fmaf_rn(a.x, b.x, dot);
        dot = __fmaf_rn(a.y, b.y, dot);
        dot = __fmaf_rn(a.z, b.z, dot);
        dot = __fmaf_rn(a.w, b.w, dot);
    }
    return __fmaf_rn(-2.0f, dot, __fadd_rn(d_sz[t], d_se[k]));
}

// ---------------------------------------------------------------- L1: prep
__global__ void __launch_bounds__(256) vq_prep(const float* __restrict__ z,
                                               const float* __restrict__ cb) {
    int b = blockIdx.x, tid = threadIdx.x;
    int w = tid >> 5, lane = tid & 31;
    int row = b * 8 + w;
    bool isz = row < N_TOK;
    const float* src = isz ? z : cb;
    int r = isz ? row : row - N_TOK;

    float2 v = *(const float2*)&src[(size_t)r * ED + lane * 2];
    float sc = isz ? -2.0f : 1.0f;
    float m0 = sc * v.x, m1 = sc * v.y;
    __half h0 = __float2half_rn(m0), h1 = __float2half_rn(m1);
    __half2 hh; hh.x = h0; hh.y = h1;
    if (isz) {
        float l0 = m0 - __half2float(h0), l1 = m1 - __half2float(h1);
        __half2 ll; ll.x = __float2half_rn(l0); ll.y = __float2half_rn(l1);
        ((__half2*)d_zh)[(size_t)r * 32 + lane] = hh;
        ((__half2*)d_zl)[(size_t)r * 32 + lane] = ll;
    } else {
        ((__half2*)d_eh)[(size_t)r * 32 + lane] = hh;
        d_cbT[(size_t)(2 * lane)     * NE + r] = v.x;
        d_cbT[(size_t)(2 * lane + 1) * NE + r] = v.y;
    }

    float s = __fmaf_rn(v.x, v.x, v.y * v.y);
    #pragma unroll
    for (int o = 16; o; o >>= 1) s += __shfl_xor_sync(0xffffffffu, s, o);
    if (lane == 0) (isz ? d_sz : d_se)[r] = s;
}

// ---------------------------------------------------------------- L2: zero
__global__ void __launch_bounds__(256) vq_zero() {
    int i = blockIdx.x * 256 + threadIdx.x;
    if (i < NE) d_counts[i] = 0;
    if (i == 0) d_nflag = 0;
}

// ---------------------------------------------------------------- L3: main
static __device__ __forceinline__ void load_b(uint32_t sb, int ch, int buf) {
    int tid = threadIdx.x;
    size_t k0 = (size_t)ch * BN;
    uint32_t bh = sb + OFF_B + (uint32_t)buf * 16384u;
    #pragma unroll
    for (int p = 0; p < 2; p++) {
        int l = tid + p * NTHR;
        int row = l >> 3, seg = l & 7;
        uint32_t sw = swz((uint32_t)(row * 128 + seg * 16));
        size_t g = ((k0 + row) * ED + seg * 8) * 2;
        CP_ASYNC16(bh + sw, (const char*)d_eh + g);
    }
}

__global__ void __launch_bounds__(NTHR, 1) vq_main() {
    extern __shared__ char smem[];
    uint32_t sb = smem_u32(smem);
    const int tid = threadIdx.x;
    const int w = tid >> 5, lid = tid & 31;
    const int rowgrp = w & 7;
    const int nhalf = w >> 3;
    const int m0 = blockIdx.x * BM;

    #pragma unroll
    for (int p = 0; p < 2; p++) {
        int l = tid + p * NTHR;
        int row = l >> 3, seg = l & 7;
        uint32_t sw = swz((uint32_t)(row * 128 + seg * 16));
        size_t g = (((size_t)(m0 + row)) * ED + seg * 8) * 2;
        *(uint4*)(smem + OFF_A + sw)         = *(const uint4*)((const char*)d_zh + g);
        *(uint4*)(smem + OFF_A + 16384 + sw) = *(const uint4*)((const char*)d_zl + g);
    }
    float* ses = (float*)(smem + OFF_SES);
    for (int i = tid; i < NE; i += NTHR) ses[i] = d_se[i];
    __syncthreads();

    uint32_t ah[4][4], al[4][4];
    {
        int arow = rowgrp * 16 + (lid & 7) + ((lid >> 3) & 1) * 8;
        #pragma unroll
        for (int ks = 0; ks < 4; ks++) {
            uint32_t off = swz((uint32_t)(arow * 128 + ks * 32 + (lid >> 4) * 16));
            ldsm4(ah[ks][0], ah[ks][1], ah[ks][2], ah[ks][3], sb + OFF_A + off);
            ldsm4(al[ks][0], al[ks][1], al[ks][2], al[ks][3], sb + OFF_A + 16384u + off);
        }
    }

    float v00 = 3.4e38f, v01 = 3.4e38f, v02 = 3.4e38f;
    float v10 = 3.4e38f, v11 = 3.4e38f, v12 = 3.4e38f;
    int   i00 = 0x7fffffff, i01 = 0x7fffffff, i10 = 0x7fffffff, i11 = 0x7fffffff;

    load_b(sb, 0, 0);
    CP_COMMIT();

    const int brow_l = (lid & 7) + ((lid >> 3) & 1) * 8;
    const int boff_l = (lid >> 4) * 16;

    for (int ch = 0; ch < NCH; ch++) {
        if (ch + 1 < NCH) { load_b(sb, ch + 1, (ch + 1) & 1); CP_COMMIT(); }
        if (ch + 1 < NCH) CP_WAIT(1); else CP_WAIT(0);
        __syncthreads();

        uint32_t bbase = sb + OFF_B + (uint32_t)((ch & 1) * 16384);

        #pragma unroll
        for (int nt2 = 0; nt2 < 4; nt2++) {
            int codebase = nhalf * 64 + nt2 * 16;
            float aE[4] = {0.f, 0.f, 0.f, 0.f};
            float aO[4] = {0.f, 0.f, 0.f, 0.f};
            #pragma unroll
            for (int ks = 0; ks < 4; ks++) {
                uint32_t sa = swz((uint32_t)((codebase + brow_l) * 128 + ks * 32 + boff_l));
                uint32_t h0, h1, h2, h3;
                ldsm4(h0, h1, h2, h3, bbase + sa);
                mma_f16(aE, ah[ks], h0, h2);
                mma_f16(aO, ah[ks], h1, h3);
                mma_f16(aE, al[ks], h0, h2);
                mma_f16(aO, al[ks], h1, h3);
            }
            int cE = codebase + 2 * (lid & 3);
            float2 sE = *(const float2*)&ses[ch * BN + cE];
            float2 sO = *(const float2*)&ses[ch * BN + cE + 8];
            int kg = ch * BN + cE;
            float dv;
            dv = __fadd_rn(aE[0], sE.x); UPD3(v00, i00, v01, i01, v02, dv, kg);
            dv = __fadd_rn(aE[1], sE.y); UPD3(v00, i00, v01, i01, v02, dv, kg + 1);
            dv = __fadd_rn(aO[0], sO.x); UPD3(v00, i00, v01, i01, v02, dv, kg + 8);
            dv = __fadd_rn(aO[1], sO.y); UPD3(v00, i00, v01, i01, v02, dv, kg + 9);
            dv = __fadd_rn(aE[2], sE.x); UPD3(v10, i10, v11, i11, v12, dv, kg);
            dv = __fadd_rn(aE[3], sE.y); UPD3(v10, i10, v11, i11, v12, dv, kg + 1);
            dv = __fadd_rn(aO[2], sO.x); UPD3(v10, i10, v11, i11, v12, dv, kg + 8);
            dv = __fadd_rn(aO[3], sO.y); UPD3(v10, i10, v11, i11, v12, dv, kg + 9);
        }
        __syncthreads();
    }

    int t0 = m0 + rowgrp * 16 + (lid >> 2);
    int slot = nhalf * 8 + (lid & 3) * 2;
    int slot2 = nhalf * 4 + (lid & 3);
    *(float2*)(d_bd + (size_t)t0 * 16 + slot)       = make_float2(v00, v01);
    *(int2*)  (d_bi + (size_t)t0 * 16 + slot)       = make_int2(i00, i01);
    *(float2*)(d_bd + (size_t)(t0 + 8) * 16 + slot) = make_float2(v10, v11);
    *(int2*)  (d_bi + (size_t)(t0 + 8) * 16 + slot) = make_int2(i10, i11);
    d_b2[(size_t)t0 * 8 + slot2]       = v02;
    d_b2[(size_t)(t0 + 8) * 8 + slot2] = v12;
}

// ---------------------------------------------------------------- L4: resolve
// Warp per token. Certified / in-window exact rescore inline; deep-risk
// (a thread's 3rd-best in window) -> flag for block-parallel exact kernel.
__global__ void __launch_bounds__(256) vq_resolve(const float* __restrict__ z,
                                                  const float* __restrict__ cb,
                                                  float* __restrict__ out) {
    int t = (blockIdx.x * 256 + threadIdx.x) >> 5;
    int l = threadIdx.x & 31;

    float v = 3.4e38f; int ix = 0x7fffffff;
    if (l < 16) { v = d_bd[(size_t)t * 16 + l]; ix = d_bi[(size_t)t * 16 + l]; }
    float v2 = (l < 8) ? d_b2[(size_t)t * 8 + l] : 3.4e38f;

    float gv = v; int gi = ix;
    #pragma unroll
    for (int o = 16; o; o >>= 1) {
        float ov = __shfl_xor_sync(0xffffffffu, gv, o);
        int   oi = __shfl_xor_sync(0xffffffffu, gi, o);
        if (ov < gv || (ov == gv && oi < gi)) { gv = ov; gi = oi; }
    }
    float thr = gv + EPSW;

    unsigned deepm = __ballot_sync(0xffffffffu, v2 <= thr);
    if (deepm) {
        if (l == 0) { int p = atomicAdd(&d_nflag, 1); d_flag[p] = t; }
        return;                                   // vq_deep finishes this token
    }

    bool inw = (l < 16) && (v <= thr);
    unsigned candm = __ballot_sync(0xffffffffu, inw);
    int winner = gi;
    if (__popc(candm) > 1) {
        float bv = 3.4e38f; int bk = 0x7fffffff;
        if (inw) { bv = exact_chain(z, cb, t, ix); bk = ix; }
        #pragma unroll
        for (int o = 16; o; o >>= 1) {
            float ov = __shfl_xor_sync(0xffffffffu, bv, o);
            int   oi = __shfl_xor_sync(0xffffffffu, bk, o);
            if (ov < bv || (ov == bv && oi < bk)) { bv = ov; bk = oi; }
        }
        winner = bk;
    }

    if (l == 0) {
        out[OUT_IDX_OFF + t] = (float)winner;
        atomicAdd(&d_counts[winner], 1);
    }
    float lacc = 0.f;
    #pragma unroll
    for (int p = 0; p < 2; p++) {
        int d = l + p * 32;
        float zq = cb[(size_t)winner * ED + d];
        float zv = z[(size_t)t * ED + d];
        float tt = __fsub_rn(zq, zv);
        out[OUT_ZQ_OFF + (size_t)t * ED + d] = __fadd_rn(zv, tt);
        lacc = __fmaf_rn(tt, tt, lacc);
    }
    #pragma unroll
    for (int o = 16; o; o >>= 1) lacc += __shfl_xor_sync(0xffffffffu, lacc, o);
    if (l == 0) d_losstok[t] = lacc;
}

// ---------------------------------------------------------------- L5: deep
// Block per flagged token: full exact scan over coalesced cbT (ref chain),
// block reduce with first-index ties, then idx/zq/loss/counts writes.
__global__ void __launch_bounds__(256) vq_deep(const float* __restrict__ z,
                                               const float* __restrict__ cb,
                                               float* __restrict__ out) {
    __shared__ float s_z[ED];
    __shared__ float s_bv[256];
    __shared__ int   s_bi[256];
    __shared__ int   s_win;
    int tid = threadIdx.x;

    for (int i = blockIdx.x; i < d_nflag; i += gridDim.x) {
        int t = d_flag[i];
        if (tid < ED) s_z[tid] = z[(size_t)t * ED + tid];
        __syncthreads();
        float szt = d_sz[t];

        float bv = 3.4e38f; int bk = 0x7fffffff;
        #pragma unroll
        for (int j = 0; j < NE / 256; j++) {       // increasing k per thread
            int k = j * 256 + tid;
            float dot = 0.f;
            #pragma unroll
            for (int d = 0; d < ED; d++)
                dot = __fmaf_rn(s_z[d], d_cbT[(size_t)d * NE + k], dot);
            float dv = __fmaf_rn(-2.0f, dot, __fadd_rn(szt, d_se[k]));
            if (dv < bv) { bv = dv; bk = k; }
        }
        s_bv[tid] = bv; s_bi[tid] = bk;
        __syncthreads();
        #pragma unroll
        for (int st = 128; st > 0; st >>= 1) {
            if (tid < st) {
                float ov = s_bv[tid + st]; int oi = s_bi[tid + st];
                if (ov < s_bv[tid] || (ov == s_bv[tid] && oi < s_bi[tid])) {
                    s_bv[tid] = ov; s_bi[tid] = oi;
                }
            }
            __syncthreads();
        }
        if (tid == 0) {
            int wn = s_bi[0];
            s_win = wn;
            out[OUT_IDX_OFF + t] = (float)wn;
            atomicAdd(&d_counts[wn], 1);
        }
        __syncthreads();
        int wn = s_win;
        if (tid < ED) {
            float zq = cb[(size_t)wn * ED + tid];
            float zv = s_z[tid];
            float tt = __fsub_rn(zq, zv);
            out[OUT_ZQ_OFF + (size_t)t * ED + tid] = __fadd_rn(zv, tt);
            s_bv[tid] = tt * tt;
        }
        __syncthreads();
        if (tid == 0) {
            float ls = 0.f;
            #pragma unroll
            for (int d = 0; d < ED; d++) ls += s_bv[d];
            d_losstok[t] = ls;
        }
        __syncthreads();
    }
}

// ---------------------------------------------------------------- L6: finalize
__global__ void __launch_bounds__(1024) vq_finalize(float* __restrict__ out) {
    __shared__ double sh[1024];
    int tid = threadIdx.x;
    double s = 0.0;
    for (int i = tid; i < N_TOK; i += 1024) s += (double)d_losstok[i];
    sh[tid] = s;
    __syncthreads();
    #pragma unroll
    for (int st = 512; st > 0; st >>= 1) {
        if (tid < st) sh[tid] += sh[tid + st];
        __syncthreads();
    }
    if (tid == 0)
        out[0] = (float)(1.25 * sh[0] / (double)((size_t)N_TOK * ED));
    __syncthreads();

    double h = 0.0;
    for (int i = tid; i < NE; i += 1024) {
        float em = (float)d_counts[i] / (float)N_TOK;
        h += (double)(em * logf(em + 1e-10f));
    }
    sh[tid] = h;
    __syncthreads();
    #pragma unroll
    for (int st = 512; st > 0; st >>= 1) {
        if (tid < st) sh[tid] += sh[tid + st];
        __syncthreads();
    }
    if (tid == 0)
        out[OUT_PERP_OFF] = expf(-(float)sh[0]);
}

// ---------------------------------------------------------------- launch
extern "C" void kernel_launch(void* const* d_in, const int* in_sizes, int n_in,
                              void* d_out, int out_size) {
    const float* z  = (const float*)d_in[0];
    const float* cb = (const float*)d_in[1];
    float* out = (float*)d_out;

    cudaFuncSetAttribute(vq_main, cudaFuncAttributeMaxDynamicSharedMemorySize, SMEM_MAIN);

    vq_prep<<<2560, 256>>>(z, cb);              // L1
    vq_zero<<<16, 256>>>();                     // L2
    vq_main<<<NBLK, NTHR, SMEM_MAIN>>>();       // L3
    vq_resolve<<<N_TOK / 8, 256>>>(z, cb, out); // L4  <- profiled slot
    vq_deep<<<512, 256>>>(z, cb, out);          // L5
    vq_finalize<<<1, 1024>>>(out);              // L6
}